// round 8
// baseline (speedup 1.0000x reference)
#include <cuda_runtime.h>
#include <math.h>

#define HW      131072      // 256*512
#define W_IMG   512
#define H_IMG   256
#define NC      256
#define NB      2
#define NOUT    16          // 13 pos + 1 reg + 2 off

typedef unsigned long long ull;

// Scratch for evident = relu(pos conv): [2,13,H,W]
__device__ float g_ev[NB * 13 * HW];

// Weights as duplicated {w,w} f32x2 pairs + biases, staged to __constant__.
struct WBlob {
    ull   w[NC * NOUT];   // [c*16+o] = {w_oc, w_oc}
    float bias[NOUT];
};
__device__   WBlob g_wblob;
__constant__ WBlob c_w;

// ---------------- compile-time Hough region geometry ----------------
__host__ __device__ constexpr int region_of(int ys, int xs) {
    int r2 = ys * ys + xs * xs;
    if (r2 <= 4) return 0;
    int ring = (r2 <= 64) ? 0 : (r2 <= 256) ? 1 : 2;
    int bin = 0;
    if (ys > 0)      bin = (xs > 0) ? 0 : 1;
    else if (ys < 0) bin = (xs < 0) ? 2 : 3;
    else             bin = (xs > 0) ? 0 : 2;   // ys==0 row (origin is r2<=4)
    return 1 + ring * 4 + bin;
}

struct SegTab {
    short iy[512];
    short a[512];
    short b[512];
    int   start[14];
    float w[13];
};

__host__ __device__ constexpr SegTab make_segs() {
    SegTab t{};
    int cnt[13] = {};
    for (int iy = 0; iy < 33; iy++)
        for (int ix = 0; ix < 33; ix++)
            cnt[region_of(16 - iy, 16 - ix)]++;
    int pos = 0;
    for (int r = 0; r < 13; r++) {
        t.start[r] = pos;
        t.w[r] = 1.0f / (float)cnt[r];
        for (int iy = 0; iy < 33; iy++) {
            int ix = 0;
            while (ix < 33) {
                if (region_of(16 - iy, 16 - ix) == r) {
                    int a0 = ix;
                    while (ix < 33 && region_of(16 - iy, 16 - ix) == r) ix++;
                    t.iy[pos] = (short)iy;
                    t.a[pos]  = (short)a0;
                    t.b[pos]  = (short)(ix - 1);
                    pos++;
                } else ix++;
            }
        }
    }
    t.start[13] = pos;
    return t;
}

// ---------------- prep: build duplicated weight pairs in g_wblob ----------
__global__ void k_prep(
    const float* __restrict__ pos_w, const float* __restrict__ pos_b,
    const float* __restrict__ reg_w, const float* __restrict__ reg_b,
    const float* __restrict__ off_w, const float* __restrict__ off_b)
{
    int i = blockIdx.x * 256 + threadIdx.x;   // 0..4095
    if (i < NC * NOUT) {
        int c = i >> 4, o = i & 15;
        float w = (o < 13) ? pos_w[o * NC + c]
                : (o == 13) ? reg_w[c]
                : off_w[(o - 14) * NC + c];
        unsigned int u = __float_as_uint(w);
        g_wblob.w[i] = (ull)u | ((ull)u << 32);
    }
    if (i < NOUT)
        g_wblob.bias[i] = (i < 13) ? pos_b[i] : (i == 13) ? reg_b[0] : off_b[i - 14];
}

// dummy for ncu launch-index parity (makes -s 5 land on k_head)
__global__ void k_nop() {}

// ---------------- Kernel A: fused 1x1 convs (16 out channels) -------------
// 2 px/thread, 256 thr/block, occ 3 (24 warps/SM) for latency hiding.
// Weights from __constant__ (constant port; no smem crossbar, no LSU).
// CBATCH=16 front-batched LDG.64 keeps MLP high.
#define FMA2(d, a, b) asm("fma.rn.f32x2 %0, %1, %2, %0;" : "+l"(d) : "l"(a), "l"(b))
#define CBATCH 16

__global__ void __launch_bounds__(256, 3) k_head(
    const float* __restrict__ x, float* __restrict__ out)
{
    const int tid = threadIdx.x;
    const int b   = blockIdx.y;
    const int p0  = blockIdx.x * 512 + tid * 2;   // 2 consecutive px
    const float* xp = x + (size_t)b * NC * HW + p0;

    ull acc[NOUT];
    #pragma unroll
    for (int o = 0; o < NOUT; o++) acc[o] = 0ull;

    #pragma unroll 1
    for (int cb = 0; cb < NC; cb += CBATCH) {
        ull xv[CBATCH];
        #pragma unroll
        for (int j = 0; j < CBATCH; j++)
            xv[j] = *reinterpret_cast<const ull*>(xp + (size_t)(cb + j) * HW);

        #pragma unroll
        for (int j = 0; j < CBATCH; j++) {
            #pragma unroll
            for (int o = 0; o < NOUT; o++)
                FMA2(acc[o], xv[j], c_w.w[(cb + j) * NOUT + o]);
        }
    }

    // Epilogue: bias, relu for evident, route to scratch / out
    #pragma unroll
    for (int o = 0; o < NOUT; o++) {
        float bias = c_w.bias[o];
        float2 v;
        v.x = __uint_as_float((unsigned)(acc[o]))       + bias;
        v.y = __uint_as_float((unsigned)(acc[o] >> 32)) + bias;
        if (o < 13) {
            v.x = fmaxf(v.x, 0.f); v.y = fmaxf(v.y, 0.f);
            float* dst = g_ev + (size_t)(b * 13 + o) * HW;
            *reinterpret_cast<float2*>(dst + p0) = v;
        } else if (o == 13) {
            float* dst = out + 2 * HW + (size_t)b * HW;   // x_reg block
            *reinterpret_cast<float2*>(dst + p0) = v;
        } else {
            float* dst = out + 4 * HW + (size_t)(b * 2 + (o - 14)) * HW; // x_off
            *reinterpret_cast<float2*>(dst + p0) = v;
        }
    }
}

// ---------------- Kernel B: Hough vote conv + sigmoid ----------------
// (unchanged from R7: measured 31.1-31.4us three times)
#define PSTR 65

template<int R>
__device__ __forceinline__ float gather_region(const float* __restrict__ buf, int pbase) {
    constexpr SegTab t = make_segs();
    constexpr int j0 = t.start[R];
    constexpr int j1 = t.start[R + 1];
    float s0 = 0.f, s1 = 0.f, s2 = 0.f, s3 = 0.f;
    #pragma unroll
    for (int j = j0; j < j1; j++) {
        int ro = t.iy[j] * PSTR;
        float d = buf[pbase + ro + t.b[j] + 1] - buf[pbase + ro + t.a[j]];
        int lane4 = j & 3;
        if      (lane4 == 0) s0 += d;
        else if (lane4 == 1) s1 += d;
        else if (lane4 == 2) s2 += d;
        else                 s3 += d;
    }
    return ((s0 + s1) + (s2 + s3)) * t.w[R];
}

template<int R> struct ChanLoop {
    static __device__ __forceinline__ float run(
        int b, int y0, int x0, int lane, int wrp, int pbase,
        float* __restrict__ sP0, float* __restrict__ sP1)
    {
        float* buf = (R & 1) ? sP1 : sP0;
        const float* ev = g_ev + (size_t)(b * 13 + R) * HW;

        #pragma unroll
        for (int k = 0; k < 2; k++) {
            int row = 2 * wrp + k;
            int gy  = y0 + row - 16;
            int gx  = x0 + 2 * lane - 16;
            float v0 = 0.f, v1 = 0.f;
            if ((unsigned)gy < (unsigned)H_IMG) {
                const float* rp = ev + gy * W_IMG;
                if ((unsigned)gx       < (unsigned)W_IMG) v0 = rp[gx];
                if ((unsigned)(gx + 1) < (unsigned)W_IMG) v1 = rp[gx + 1];
            }
            float s = v0 + v1;
            float inc = s;
            #pragma unroll
            for (int d = 1; d < 32; d <<= 1) {
                float n = __shfl_up_sync(0xffffffffu, inc, d);
                if (lane >= d) inc += n;
            }
            float excl = inc - s;
            float* rowp = buf + row * PSTR;   // rowp[j] = sum of cols [0, j)
            if (lane == 0) rowp[0] = 0.f;
            rowp[2 * lane + 1] = excl + v0;
            rowp[2 * lane + 2] = inc;
        }
        __syncthreads();
        float part = gather_region<R>(buf, pbase);
        return part + ChanLoop<R + 1>::run(b, y0, x0, lane, wrp, pbase, sP0, sP1);
    }
};

template<> struct ChanLoop<13> {
    static __device__ __forceinline__ float run(int, int, int, int, int, int, float*, float*) {
        return 0.f;
    }
};

__global__ void __launch_bounds__(1024) k_hough(float* __restrict__ out)
{
    __shared__ float sP[2][64 * PSTR];

    const int tid  = threadIdx.x;
    const int lane = tid & 31;
    const int wrp  = tid >> 5;
    const int b  = blockIdx.z;
    const int y0 = blockIdx.y * 32;
    const int x0 = blockIdx.x * 32;
    const int pbase = wrp * PSTR + lane;

    float score = ChanLoop<0>::run(b, y0, x0, lane, wrp, pbase, sP[0], sP[1]);

    out[(size_t)b * HW + (y0 + wrp) * W_IMG + (x0 + lane)] = 1.f / (1.f + expf(-score));
}

// ---------------- launch ----------------
extern "C" void kernel_launch(void* const* d_in, const int* in_sizes, int n_in,
                              void* d_out, int out_size)
{
    const float* x     = (const float*)d_in[0];
    const float* pos_w = (const float*)d_in[1];
    const float* pos_b = (const float*)d_in[2];
    const float* reg_w = (const float*)d_in[3];
    const float* reg_b = (const float*)d_in[4];
    const float* off_w = (const float*)d_in[5];
    const float* off_b = (const float*)d_in[6];
    float* out = (float*)d_out;

    // 1) build duplicated weight pairs in device global
    k_prep<<<16, 256>>>(pos_w, pos_b, reg_w, reg_b, off_w, off_b);

    // 2) stage into __constant__ (D2D memcpy node; graph-capturable)
    void* src = nullptr;
    cudaGetSymbolAddress(&src, g_wblob);
    cudaMemcpyToSymbolAsync(c_w, src, sizeof(WBlob), 0, cudaMemcpyDeviceToDevice, 0);

    // 3) heads (profiled: with 4 kernels/call, ncu -s 5 lands here)
    dim3 gA(HW / 512, NB);           // 256 x 2 = 512 blocks
    k_head<<<gA, 256>>>(x, out);

    // 4) parity dummy so launch idx 5 == k_head under ncu
    k_nop<<<1, 32>>>();

    // 5) hough vote + sigmoid
    dim3 gB(W_IMG / 32, H_IMG / 32, NB);
    k_hough<<<gB, 1024>>>(out);
}

// round 9
// speedup vs baseline: 1.4561x; 1.4561x over previous
#include <cuda_runtime.h>
#include <math.h>

#define HW      131072      // 256*512
#define W_IMG   512
#define H_IMG   256
#define NC      256
#define NB      2
#define NOUT    16          // 13 pos + 1 reg + 2 off

typedef unsigned long long ull;

// Scratch for evident = relu(pos conv): [2,13,H,W]
__device__ float g_ev[NB * 13 * HW];

// ---------------- compile-time Hough region geometry ----------------
__host__ __device__ constexpr int region_of(int ys, int xs) {
    int r2 = ys * ys + xs * xs;
    if (r2 <= 4) return 0;
    int ring = (r2 <= 64) ? 0 : (r2 <= 256) ? 1 : 2;
    int bin = 0;
    if (ys > 0)      bin = (xs > 0) ? 0 : 1;
    else if (ys < 0) bin = (xs < 0) ? 2 : 3;
    else             bin = (xs > 0) ? 0 : 2;   // ys==0 row (origin is r2<=4)
    return 1 + ring * 4 + bin;
}

struct SegTab {
    short iy[512];
    short a[512];
    short b[512];
    int   start[14];
    float w[13];
};

__host__ __device__ constexpr SegTab make_segs() {
    SegTab t{};
    int cnt[13] = {};
    for (int iy = 0; iy < 33; iy++)
        for (int ix = 0; ix < 33; ix++)
            cnt[region_of(16 - iy, 16 - ix)]++;
    int pos = 0;
    for (int r = 0; r < 13; r++) {
        t.start[r] = pos;
        t.w[r] = 1.0f / (float)cnt[r];
        for (int iy = 0; iy < 33; iy++) {
            int ix = 0;
            while (ix < 33) {
                if (region_of(16 - iy, 16 - ix) == r) {
                    int a0 = ix;
                    while (ix < 33 && region_of(16 - iy, 16 - ix) == r) ix++;
                    t.iy[pos] = (short)iy;
                    t.a[pos]  = (short)a0;
                    t.b[pos]  = (short)(ix - 1);
                    pos++;
                } else ix++;
            }
        }
    }
    t.start[13] = pos;
    return t;
}

// ---------------- Kernel A: fused 1x1 convs (16 out channels) -------------
// TLB-friendly geometry: 1 block/SM (512 threads), 4 px/thread, grid = 128
// blocks = SINGLE wave. Each block touches only ~70 distinct 2MB pages
// (4 channels share a page; all warps march channels together), fitting the
// 128-entry TLB. Weights in shared as duplicated {w,w} pairs (broadcast LDS).
#define FMA2(d, a, b) asm("fma.rn.f32x2 %0, %1, %2, %0;" : "+l"(d) : "l"(a), "l"(b))
#define CB 8

__global__ void __launch_bounds__(512, 1) k_head(
    const float* __restrict__ x,
    const float* __restrict__ pos_w, const float* __restrict__ pos_b,
    const float* __restrict__ reg_w, const float* __restrict__ reg_b,
    const float* __restrict__ off_w, const float* __restrict__ off_b,
    float* __restrict__ out)
{
    __shared__ __align__(16) ull wdup[NC * NOUT];

    const int tid = threadIdx.x;
    for (int i = tid; i < NC * NOUT; i += 512) {
        int c = i >> 4, o = i & 15;
        float w = (o < 13) ? pos_w[o * NC + c]
                : (o == 13) ? reg_w[c]
                : off_w[(o - 14) * NC + c];
        unsigned int u = __float_as_uint(w);
        wdup[i] = (ull)u | ((ull)u << 32);
    }
    __syncthreads();

    const int b  = blockIdx.y;
    const int p0 = blockIdx.x * 2048 + tid * 4;   // 4 consecutive px
    const float* xp = x + (size_t)b * NC * HW + p0;

    ull acc[2][NOUT];
    #pragma unroll
    for (int g = 0; g < 2; g++)
        #pragma unroll
        for (int o = 0; o < NOUT; o++) acc[g][o] = 0ull;

    #pragma unroll 1
    for (int cb = 0; cb < NC; cb += CB) {
        // front-batched independent loads (MLP = CB)
        ulonglong2 xv[CB];
        #pragma unroll
        for (int j = 0; j < CB; j++)
            xv[j] = *reinterpret_cast<const ulonglong2*>(xp + (size_t)(cb + j) * HW);

        #pragma unroll
        for (int j = 0; j < CB; j++) {
            const ulonglong2* wp =
                reinterpret_cast<const ulonglong2*>(wdup + (cb + j) * NOUT);
            #pragma unroll
            for (int k = 0; k < 8; k++) {
                ulonglong2 wv = wp[k];   // {w(2k),w(2k)}, {w(2k+1),w(2k+1)}
                FMA2(acc[0][2 * k],     xv[j].x, wv.x);
                FMA2(acc[1][2 * k],     xv[j].y, wv.x);
                FMA2(acc[0][2 * k + 1], xv[j].x, wv.y);
                FMA2(acc[1][2 * k + 1], xv[j].y, wv.y);
            }
        }
    }

    // Epilogue: bias, relu for evident, route to scratch / out
    #pragma unroll
    for (int o = 0; o < NOUT; o++) {
        float bias = (o < 13) ? pos_b[o] : (o == 13) ? reg_b[0] : off_b[o - 14];
        float4 v;
        v.x = __uint_as_float((unsigned)(acc[0][o]))       + bias;
        v.y = __uint_as_float((unsigned)(acc[0][o] >> 32)) + bias;
        v.z = __uint_as_float((unsigned)(acc[1][o]))       + bias;
        v.w = __uint_as_float((unsigned)(acc[1][o] >> 32)) + bias;
        if (o < 13) {
            v.x = fmaxf(v.x, 0.f); v.y = fmaxf(v.y, 0.f);
            v.z = fmaxf(v.z, 0.f); v.w = fmaxf(v.w, 0.f);
            float* dst = g_ev + (size_t)(b * 13 + o) * HW;
            *reinterpret_cast<float4*>(dst + p0) = v;
        } else if (o == 13) {
            float* dst = out + 2 * HW + (size_t)b * HW;   // x_reg block
            *reinterpret_cast<float4*>(dst + p0) = v;
        } else {
            float* dst = out + 4 * HW + (size_t)(b * 2 + (o - 14)) * HW; // x_off
            *reinterpret_cast<float4*>(dst + p0) = v;
        }
    }
}

// ---------------- Kernel B: Hough vote conv + sigmoid ----------------
// (unchanged: measured 31.1-31.4us four times)
#define PSTR 65

template<int R>
__device__ __forceinline__ float gather_region(const float* __restrict__ buf, int pbase) {
    constexpr SegTab t = make_segs();
    constexpr int j0 = t.start[R];
    constexpr int j1 = t.start[R + 1];
    float s0 = 0.f, s1 = 0.f, s2 = 0.f, s3 = 0.f;
    #pragma unroll
    for (int j = j0; j < j1; j++) {
        int ro = t.iy[j] * PSTR;
        float d = buf[pbase + ro + t.b[j] + 1] - buf[pbase + ro + t.a[j]];
        int lane4 = j & 3;
        if      (lane4 == 0) s0 += d;
        else if (lane4 == 1) s1 += d;
        else if (lane4 == 2) s2 += d;
        else                 s3 += d;
    }
    return ((s0 + s1) + (s2 + s3)) * t.w[R];
}

template<int R> struct ChanLoop {
    static __device__ __forceinline__ float run(
        int b, int y0, int x0, int lane, int wrp, int pbase,
        float* __restrict__ sP0, float* __restrict__ sP1)
    {
        float* buf = (R & 1) ? sP1 : sP0;
        const float* ev = g_ev + (size_t)(b * 13 + R) * HW;

        #pragma unroll
        for (int k = 0; k < 2; k++) {
            int row = 2 * wrp + k;
            int gy  = y0 + row - 16;
            int gx  = x0 + 2 * lane - 16;
            float v0 = 0.f, v1 = 0.f;
            if ((unsigned)gy < (unsigned)H_IMG) {
                const float* rp = ev + gy * W_IMG;
                if ((unsigned)gx       < (unsigned)W_IMG) v0 = rp[gx];
                if ((unsigned)(gx + 1) < (unsigned)W_IMG) v1 = rp[gx + 1];
            }
            float s = v0 + v1;
            float inc = s;
            #pragma unroll
            for (int d = 1; d < 32; d <<= 1) {
                float n = __shfl_up_sync(0xffffffffu, inc, d);
                if (lane >= d) inc += n;
            }
            float excl = inc - s;
            float* rowp = buf + row * PSTR;   // rowp[j] = sum of cols [0, j)
            if (lane == 0) rowp[0] = 0.f;
            rowp[2 * lane + 1] = excl + v0;
            rowp[2 * lane + 2] = inc;
        }
        __syncthreads();
        float part = gather_region<R>(buf, pbase);
        return part + ChanLoop<R + 1>::run(b, y0, x0, lane, wrp, pbase, sP0, sP1);
    }
};

template<> struct ChanLoop<13> {
    static __device__ __forceinline__ float run(int, int, int, int, int, int, float*, float*) {
        return 0.f;
    }
};

__global__ void __launch_bounds__(1024) k_hough(float* __restrict__ out)
{
    __shared__ float sP[2][64 * PSTR];

    const int tid  = threadIdx.x;
    const int lane = tid & 31;
    const int wrp  = tid >> 5;
    const int b  = blockIdx.z;
    const int y0 = blockIdx.y * 32;
    const int x0 = blockIdx.x * 32;
    const int pbase = wrp * PSTR + lane;

    float score = ChanLoop<0>::run(b, y0, x0, lane, wrp, pbase, sP[0], sP[1]);

    out[(size_t)b * HW + (y0 + wrp) * W_IMG + (x0 + lane)] = 1.f / (1.f + expf(-score));
}

// ---------------- launch ----------------
extern "C" void kernel_launch(void* const* d_in, const int* in_sizes, int n_in,
                              void* d_out, int out_size)
{
    const float* x     = (const float*)d_in[0];
    const float* pos_w = (const float*)d_in[1];
    const float* pos_b = (const float*)d_in[2];
    const float* reg_w = (const float*)d_in[3];
    const float* reg_b = (const float*)d_in[4];
    const float* off_w = (const float*)d_in[5];
    const float* off_b = (const float*)d_in[6];
    float* out = (float*)d_out;

    dim3 gA(HW / 2048, NB);          // 64 x 2 = 128 blocks, 1/SM, single wave
    k_head<<<gA, 512>>>(x, pos_w, pos_b, reg_w, reg_b, off_w, off_b, out);

    dim3 gB(W_IMG / 32, H_IMG / 32, NB);
    k_hough<<<gB, 1024>>>(out);
}

// round 10
// speedup vs baseline: 1.4613x; 1.0036x over previous
#include <cuda_runtime.h>
#include <math.h>

#define HW      131072      // 256*512
#define W_IMG   512
#define H_IMG   256
#define NC      256
#define NB      2
#define NOUT    16          // 13 pos + 1 reg + 2 off

typedef unsigned long long ull;

// Scratch for evident = relu(pos conv): [2,13,H,W]
__device__ float g_ev[NB * 13 * HW];

// ---------------- compile-time Hough region geometry ----------------
__host__ __device__ constexpr int region_of(int ys, int xs) {
    int r2 = ys * ys + xs * xs;
    if (r2 <= 4) return 0;
    int ring = (r2 <= 64) ? 0 : (r2 <= 256) ? 1 : 2;
    int bin = 0;
    if (ys > 0)      bin = (xs > 0) ? 0 : 1;
    else if (ys < 0) bin = (xs < 0) ? 2 : 3;
    else             bin = (xs > 0) ? 0 : 2;   // ys==0 row (origin is r2<=4)
    return 1 + ring * 4 + bin;
}

struct SegTab {
    short iy[512];
    short a[512];
    short b[512];
    int   start[14];
    float w[13];
};

__host__ __device__ constexpr SegTab make_segs() {
    SegTab t{};
    int cnt[13] = {};
    for (int iy = 0; iy < 33; iy++)
        for (int ix = 0; ix < 33; ix++)
            cnt[region_of(16 - iy, 16 - ix)]++;
    int pos = 0;
    for (int r = 0; r < 13; r++) {
        t.start[r] = pos;
        t.w[r] = 1.0f / (float)cnt[r];
        for (int iy = 0; iy < 33; iy++) {
            int ix = 0;
            while (ix < 33) {
                if (region_of(16 - iy, 16 - ix) == r) {
                    int a0 = ix;
                    while (ix < 33 && region_of(16 - iy, 16 - ix) == r) ix++;
                    t.iy[pos] = (short)iy;
                    t.a[pos]  = (short)a0;
                    t.b[pos]  = (short)(ix - 1);
                    pos++;
                } else ix++;
            }
        }
    }
    t.start[13] = pos;
    return t;
}

// ---------------- Kernel A: fused 1x1 convs (16 out channels) -------------
// TLB-friendly geometry (confirmed R9): per-block page footprint is set by the
// channel dimension (~80 pages), so we shrink px/block and run ONE block on
// EVERY SM: 148 blocks x 443 four-px groups (512 thr, 443 active = 14 warps).
#define FMA2(d, a, b) asm("fma.rn.f32x2 %0, %1, %2, %0;" : "+l"(d) : "l"(a), "l"(b))
#define CB 8
#define NGRP  65536          // total 4-px groups = NB*HW/4
#define GPB   443            // ceil(NGRP / 148)

__global__ void __launch_bounds__(512, 1) k_head(
    const float* __restrict__ x,
    const float* __restrict__ pos_w, const float* __restrict__ pos_b,
    const float* __restrict__ reg_w, const float* __restrict__ reg_b,
    const float* __restrict__ off_w, const float* __restrict__ off_b,
    float* __restrict__ out)
{
    __shared__ __align__(16) ull wdup[NC * NOUT];

    const int tid = threadIdx.x;
    for (int i = tid; i < NC * NOUT; i += 512) {
        int c = i >> 4, o = i & 15;
        float w = (o < 13) ? pos_w[o * NC + c]
                : (o == 13) ? reg_w[c]
                : off_w[(o - 14) * NC + c];
        unsigned int u = __float_as_uint(w);
        wdup[i] = (ull)u | ((ull)u << 32);
    }
    __syncthreads();

    const int g = blockIdx.x * GPB + tid;          // 4-px group id
    if (tid >= GPB || g >= NGRP) return;           // after the only barrier
    const int b  = g >> 15;                        // g / (HW/4)
    const int p0 = (g & 32767) * 4;
    const float* xp = x + (size_t)b * NC * HW + p0;

    ull acc[2][NOUT];
    #pragma unroll
    for (int gi = 0; gi < 2; gi++)
        #pragma unroll
        for (int o = 0; o < NOUT; o++) acc[gi][o] = 0ull;

    #pragma unroll 1
    for (int cb = 0; cb < NC; cb += CB) {
        // front-batched independent loads (MLP = CB)
        ulonglong2 xv[CB];
        #pragma unroll
        for (int j = 0; j < CB; j++)
            xv[j] = *reinterpret_cast<const ulonglong2*>(xp + (size_t)(cb + j) * HW);

        #pragma unroll
        for (int j = 0; j < CB; j++) {
            const ulonglong2* wp =
                reinterpret_cast<const ulonglong2*>(wdup + (cb + j) * NOUT);
            #pragma unroll
            for (int k = 0; k < 8; k++) {
                ulonglong2 wv = wp[k];   // {w(2k),w(2k)}, {w(2k+1),w(2k+1)}
                FMA2(acc[0][2 * k],     xv[j].x, wv.x);
                FMA2(acc[1][2 * k],     xv[j].y, wv.x);
                FMA2(acc[0][2 * k + 1], xv[j].x, wv.y);
                FMA2(acc[1][2 * k + 1], xv[j].y, wv.y);
            }
        }
    }

    // Epilogue: bias, relu for evident, route to scratch / out
    #pragma unroll
    for (int o = 0; o < NOUT; o++) {
        float bias = (o < 13) ? pos_b[o] : (o == 13) ? reg_b[0] : off_b[o - 14];
        float4 v;
        v.x = __uint_as_float((unsigned)(acc[0][o]))       + bias;
        v.y = __uint_as_float((unsigned)(acc[0][o] >> 32)) + bias;
        v.z = __uint_as_float((unsigned)(acc[1][o]))       + bias;
        v.w = __uint_as_float((unsigned)(acc[1][o] >> 32)) + bias;
        if (o < 13) {
            v.x = fmaxf(v.x, 0.f); v.y = fmaxf(v.y, 0.f);
            v.z = fmaxf(v.z, 0.f); v.w = fmaxf(v.w, 0.f);
            float* dst = g_ev + (size_t)(b * 13 + o) * HW;
            *reinterpret_cast<float4*>(dst + p0) = v;
        } else if (o == 13) {
            float* dst = out + 2 * HW + (size_t)b * HW;   // x_reg block
            *reinterpret_cast<float4*>(dst + p0) = v;
        } else {
            float* dst = out + 4 * HW + (size_t)(b * 2 + (o - 14)) * HW; // x_off
            *reinterpret_cast<float4*>(dst + p0) = v;
        }
    }
}

// ---------------- Kernel B: Hough vote conv + sigmoid ----------------
// (stable at 31.1-31.4us across five rounds; only change: expf -> __expf)
#define PSTR 65

template<int R>
__device__ __forceinline__ float gather_region(const float* __restrict__ buf, int pbase) {
    constexpr SegTab t = make_segs();
    constexpr int j0 = t.start[R];
    constexpr int j1 = t.start[R + 1];
    float s0 = 0.f, s1 = 0.f, s2 = 0.f, s3 = 0.f;
    #pragma unroll
    for (int j = j0; j < j1; j++) {
        int ro = t.iy[j] * PSTR;
        float d = buf[pbase + ro + t.b[j] + 1] - buf[pbase + ro + t.a[j]];
        int lane4 = j & 3;
        if      (lane4 == 0) s0 += d;
        else if (lane4 == 1) s1 += d;
        else if (lane4 == 2) s2 += d;
        else                 s3 += d;
    }
    return ((s0 + s1) + (s2 + s3)) * t.w[R];
}

template<int R> struct ChanLoop {
    static __device__ __forceinline__ float run(
        int b, int y0, int x0, int lane, int wrp, int pbase,
        float* __restrict__ sP0, float* __restrict__ sP1)
    {
        float* buf = (R & 1) ? sP1 : sP0;
        const float* ev = g_ev + (size_t)(b * 13 + R) * HW;

        #pragma unroll
        for (int k = 0; k < 2; k++) {
            int row = 2 * wrp + k;
            int gy  = y0 + row - 16;
            int gx  = x0 + 2 * lane - 16;
            float v0 = 0.f, v1 = 0.f;
            if ((unsigned)gy < (unsigned)H_IMG) {
                const float* rp = ev + gy * W_IMG;
                if ((unsigned)gx       < (unsigned)W_IMG) v0 = rp[gx];
                if ((unsigned)(gx + 1) < (unsigned)W_IMG) v1 = rp[gx + 1];
            }
            float s = v0 + v1;
            float inc = s;
            #pragma unroll
            for (int d = 1; d < 32; d <<= 1) {
                float n = __shfl_up_sync(0xffffffffu, inc, d);
                if (lane >= d) inc += n;
            }
            float excl = inc - s;
            float* rowp = buf + row * PSTR;   // rowp[j] = sum of cols [0, j)
            if (lane == 0) rowp[0] = 0.f;
            rowp[2 * lane + 1] = excl + v0;
            rowp[2 * lane + 2] = inc;
        }
        __syncthreads();
        float part = gather_region<R>(buf, pbase);
        return part + ChanLoop<R + 1>::run(b, y0, x0, lane, wrp, pbase, sP0, sP1);
    }
};

template<> struct ChanLoop<13> {
    static __device__ __forceinline__ float run(int, int, int, int, int, int, float*, float*) {
        return 0.f;
    }
};

__global__ void __launch_bounds__(1024) k_hough(float* __restrict__ out)
{
    __shared__ float sP[2][64 * PSTR];

    const int tid  = threadIdx.x;
    const int lane = tid & 31;
    const int wrp  = tid >> 5;
    const int b  = blockIdx.z;
    const int y0 = blockIdx.y * 32;
    const int x0 = blockIdx.x * 32;
    const int pbase = wrp * PSTR + lane;

    float score = ChanLoop<0>::run(b, y0, x0, lane, wrp, pbase, sP[0], sP[1]);

    out[(size_t)b * HW + (y0 + wrp) * W_IMG + (x0 + lane)] =
        1.f / (1.f + __expf(-score));
}

// ---------------- launch ----------------
extern "C" void kernel_launch(void* const* d_in, const int* in_sizes, int n_in,
                              void* d_out, int out_size)
{
    const float* x     = (const float*)d_in[0];
    const float* pos_w = (const float*)d_in[1];
    const float* pos_b = (const float*)d_in[2];
    const float* reg_w = (const float*)d_in[3];
    const float* reg_b = (const float*)d_in[4];
    const float* off_w = (const float*)d_in[5];
    const float* off_b = (const float*)d_in[6];
    float* out = (float*)d_out;

    k_head<<<148, 512>>>(x, pos_w, pos_b, reg_w, reg_b, off_w, off_b, out);

    dim3 gB(W_IMG / 32, H_IMG / 32, NB);
    k_hough<<<gB, 1024>>>(out);
}